// round 1
// baseline (speedup 1.0000x reference)
#include <cuda_runtime.h>
#include <math.h>

#define EPSF 1e-6f
#define Bn 16
#define Tn 2048
#define LDn 256
#define NBn 32
#define BTn (Bn*Tn)
#define NCHUNK 32
#define CLEN 64

// -------- scratch (device globals: allocation-free) --------
__device__ float g_matsA[(size_t)BTn*512];   // 64 MB: [A_m | A_v] per token
__device__ float g_matsB[(size_t)BTn*512];   // 64 MB: [B_m | B_v] per token
__device__ float g_S[(size_t)BTn*512];       // 64 MB: scan state (mean|var)
__device__ float g_aggA[Bn*NCHUNK*512];
__device__ float g_aggB[Bn*NCHUNK*512];
__device__ float g_carry[Bn*NCHUNK*512];
__device__ float g_Bt[LDn*LDn];              // B_w transposed: [d][e]
__device__ float g_WMEt[LDn*LDn];            // (M_w@E_w)^T : [d][f]
__device__ float g_WCEt[LDn*LDn];            // (C_w@E_w)^T : [d][f]
__device__ float g_Abasis[NBn*LDn];
__device__ float g_initmv[512];
__device__ float g_yvar[LDn];

// ---------------- precompute: vectors + A_basis ----------------
__global__ void k_pre_small(const float* __restrict__ E_w, const float* __restrict__ D,
                            const float* __restrict__ imp, const float* __restrict__ ilv,
                            const float* __restrict__ ylv) {
    const int tid = threadIdx.x;
    if (tid < 256) {
        float s = 0.f;
        for (int k = 0; k < 256; k++) s = fmaf(E_w[k*256 + tid], imp[k], s);
        g_initmv[tid] = s;
        g_yvar[tid] = expf(ylv[tid]) + EPSF;
    } else {
        const int i = tid - 256;
        float s = 0.f;
        for (int k = 0; k < 256; k++) {
            float e = E_w[k*256 + i];
            s = fmaf(e*e, expf(ilv[k]) + EPSF, s);
        }
        g_initmv[256 + i] = s;
    }
    for (int idx = tid; idx < NBn*LDn; idx += 512)
        g_Abasis[idx] = -(expf(D[idx]) + EPSF);
}

// ---------------- precompute: transpose B_w ----------------
__global__ void k_pre_transpose(const float* __restrict__ B_w) {
    __shared__ float t[32][33];
    const int tx = threadIdx.x, ty = threadIdx.y;
    const int e = blockIdx.y*32 + ty, d = blockIdx.x*32 + tx;
    t[ty][tx] = B_w[e*256 + d];
    __syncthreads();
    const int dd = blockIdx.x*32 + ty, ee = blockIdx.y*32 + tx;
    g_Bt[dd*256 + ee] = t[tx][ty];
}

// ---------------- precompute: W_ME^T, W_CE^T (256x256x256 GEMMs) ----------------
// out[d][f] = sum_e E_w[e][d] * X[f][e]
__global__ void k_pre_gemm(const float* __restrict__ E_w, const float* __restrict__ M_w,
                           const float* __restrict__ C_w) {
    const float* X = (blockIdx.z == 0) ? M_w : C_w;
    float* out     = (blockIdx.z == 0) ? g_WMEt : g_WCEt;
    __shared__ float sE[32][33];
    __shared__ float sX[32][33];
    const int tx = threadIdx.x, ty = threadIdx.y;
    const int d0 = blockIdx.x*32, f0 = blockIdx.y*32;
    float acc = 0.f;
    for (int e0 = 0; e0 < 256; e0 += 32) {
        sE[ty][tx] = E_w[(e0+ty)*256 + d0 + tx];
        sX[ty][tx] = X[(f0+ty)*256 + e0 + tx];
        __syncthreads();
#pragma unroll
        for (int e = 0; e < 32; e++) acc = fmaf(sE[e][ty], sX[tx][e], acc);
        __syncthreads();
    }
    out[(d0+ty)*256 + f0 + tx] = acc;
}

// ---------------- main per-token kernel ----------------
// 32 tokens per block, 256 threads.
// alphas GEMM -> logits (NB=32) -> warp softmax -> A_mat -> exp terms -> mats
#define SMEM_TOKEN ((8192 + 8192 + 8224 + 1056 + 32 + 32) * 4)
__global__ void __launch_bounds__(256) k_token(const float* __restrict__ Z,
        const float* __restrict__ obs, const float* __restrict__ coeffW,
        const float* __restrict__ coeffb, float* __restrict__ alphas_out) {
    extern __shared__ float sm[];
    float* sZ    = sm;              // 32*256
    float* sAL   = sZ + 8192;       // 32*256
    float* sCW   = sAL + 8192;      // 32*257 (padded)
    float* sCoef = sCW + 8224;      // 32*33
    float* sT    = sCoef + 1056;    // 32
    float* sBias = sT + 32;         // 32

    const int tid = threadIdx.x;
    const int tok0 = blockIdx.x * 32;

    {   // load Z tile (float4, coalesced)
        const float4* zv = (const float4*)(Z + (size_t)tok0 * 256);
        float4* szv = (float4*)sZ;
#pragma unroll
        for (int i = 0; i < 8; i++) szv[tid + i*256] = zv[tid + i*256];
    }
    for (int idx = tid; idx < 8192; idx += 256)
        sCW[(idx >> 8) * 257 + (idx & 255)] = coeffW[idx];
    if (tid < 32) { sT[tid] = obs[tok0 + tid]; sBias[tid] = coeffb[tid]; }
    __syncthreads();

    // ---- alphas = Z @ B_w^T  (32 x 256) ----
    const int c0 = tid & 63;
    const int r0 = (tid >> 6) * 8;
    float acc[8][4];
#pragma unroll
    for (int r = 0; r < 8; r++)
#pragma unroll
        for (int k = 0; k < 4; k++) acc[r][k] = 0.f;

#pragma unroll 4
    for (int d = 0; d < 256; d++) {
        float w[4];
#pragma unroll
        for (int k = 0; k < 4; k++) w[k] = g_Bt[d*256 + c0 + 64*k];
        float z[8];
#pragma unroll
        for (int r = 0; r < 8; r++) z[r] = sZ[(r0 + r)*256 + d];
#pragma unroll
        for (int r = 0; r < 8; r++)
#pragma unroll
            for (int k = 0; k < 4; k++) acc[r][k] = fmaf(z[r], w[k], acc[r][k]);
    }
#pragma unroll
    for (int r = 0; r < 8; r++)
#pragma unroll
        for (int k = 0; k < 4; k++) {
            const int e = c0 + 64*k;
            const float v = acc[r][k];
            sAL[(r0 + r)*256 + e] = v;
            alphas_out[(size_t)(tok0 + r0 + r)*256 + e] = v;
        }
    __syncthreads();

    // ---- logits + softmax (one warp handles 4 tokens; lane = basis index n) ----
    const int lane = tid & 31;
    const int warp = tid >> 5;
#pragma unroll
    for (int rr = 0; rr < 4; rr++) {
        const int r = warp*4 + rr;
        const float4* arow = (const float4*)(sAL + r*256);
        const float* crow = sCW + lane*257;
        float lg = sBias[lane];
#pragma unroll 8
        for (int q = 0; q < 64; q++) {
            float4 a4 = arow[q];
            lg = fmaf(a4.x, crow[4*q+0], lg);
            lg = fmaf(a4.y, crow[4*q+1], lg);
            lg = fmaf(a4.z, crow[4*q+2], lg);
            lg = fmaf(a4.w, crow[4*q+3], lg);
        }
        float m = lg;
#pragma unroll
        for (int off = 16; off > 0; off >>= 1) m = fmaxf(m, __shfl_xor_sync(0xffffffffu, m, off));
        float e = __expf(lg - m);
        float s = e;
#pragma unroll
        for (int off = 16; off > 0; off >>= 1) s += __shfl_xor_sync(0xffffffffu, s, off);
        sCoef[r*33 + lane] = e / s;
    }
    __syncthreads();

    // ---- A_mat = coeff @ A_basis, then elementwise exp terms ----
    float am[32];
#pragma unroll
    for (int r = 0; r < 32; r++) am[r] = 0.f;
#pragma unroll 4
    for (int n = 0; n < 32; n++) {
        const float ab = g_Abasis[n*256 + tid];
#pragma unroll
        for (int r = 0; r < 32; r++) am[r] = fmaf(sCoef[r*33 + n], ab, am[r]);
    }
#pragma unroll 2
    for (int r = 0; r < 32; r++) {
        const float a = am[r];              // strictly negative
        const float t = sT[r];
        const float eAm = __expf(a * t);
        const float inv = __fdividef(1.0f, a);
        const float al = sAL[r*256 + tid];
        const float eBm = (eAm - 1.0f) * inv * al;
        const float eAv = eAm * eAm;        // exp(2At) = exp(At)^2
        const float eBv = 0.5f * (eAv - 1.0f) * inv + EPSF;
        const size_t base = (size_t)(tok0 + r) * 512;
        g_matsA[base + tid]       = eAm;
        g_matsA[base + 256 + tid] = eAv;
        g_matsB[base + tid]       = eBm;
        g_matsB[base + 256 + tid] = eBv;
    }
}

// ---------------- scan pass 1: per-chunk aggregates ----------------
__global__ void k_scan1() {
    const int bc = blockIdx.x;
    const int b = bc >> 5, ch = bc & 31;
    const int c = threadIdx.x;
    const size_t base = ((size_t)b * Tn + (size_t)ch * CLEN) * 512 + c;
    float aA = 1.f, bB = 0.f;
#pragma unroll 4
    for (int i = 0; i < CLEN; i++) {
        const float a  = g_matsA[base + (size_t)i*512];
        const float bb = g_matsB[base + (size_t)i*512];
        bB = fmaf(a, bB, bb);
        aA *= a;
    }
    g_aggA[bc*512 + c] = aA;
    g_aggB[bc*512 + c] = bB;
}

// ---------------- scan pass 2: scan aggregates, produce chunk carries ----------------
__global__ void k_scan2() {
    const int b = blockIdx.x;
    const int c = threadIdx.x;
    float s = g_initmv[c];     // h_{-1} = init_mv: folds cum_A*init_mv into the scan
#pragma unroll 4
    for (int j = 0; j < NCHUNK; j++) {
        const int idx = (b*NCHUNK + j)*512 + c;
        g_carry[idx] = s;
        s = fmaf(g_aggA[idx], s, g_aggB[idx]);
    }
}

// ---------------- scan pass 3: apply carry, write full state ----------------
__global__ void k_scan3() {
    const int bc = blockIdx.x;
    const int b = bc >> 5, ch = bc & 31;
    const int c = threadIdx.x;
    const size_t base = ((size_t)b * Tn + (size_t)ch * CLEN) * 512 + c;
    float s = g_carry[bc*512 + c];
#pragma unroll 4
    for (int i = 0; i < CLEN; i++) {
        const float a  = g_matsA[base + (size_t)i*512];
        const float bb = g_matsB[base + (size_t)i*512];
        s = fmaf(a, s, bb);
        g_S[base + (size_t)i*512] = s;
    }
}

// ---------------- output kernel: means / stds (3 fused GEMMs) ----------------
// 64 tokens per block, 512 threads. means = Sm@WME^T + Z@WCE^T ; stds = sqrt(Sv+yvar)@WME^T
#define SMEM_OUT (3 * 64 * 256 * 4)
__global__ void __launch_bounds__(512) k_out(const float* __restrict__ Zin,
        float* __restrict__ out_means, float* __restrict__ out_stds) {
    extern __shared__ float sm[];
    float* sX = sm;            // 64*256 mean-state
    float* sV = sX + 16384;    // 64*256 sqrt(var-state + yvar)
    float* sH = sV + 16384;    // 64*256 Z
    const int tid = threadIdx.x;
    const int tok0 = blockIdx.x * 64;

    for (int q = tid; q < 64*64; q += 512) {
        const int r = q >> 6;
        const int dq = (q & 63) * 4;
        const size_t tb = (size_t)(tok0 + r);
        const float4 xm = *(const float4*)(g_S + tb*512 + dq);
        const float4 xv = *(const float4*)(g_S + tb*512 + 256 + dq);
        const float4 yv = *(const float4*)(g_yvar + dq);
        const float4 zz = *(const float4*)(Zin + tb*256 + dq);
        *(float4*)(sX + r*256 + dq) = xm;
        float4 sv;
        sv.x = sqrtf(xv.x + yv.x); sv.y = sqrtf(xv.y + yv.y);
        sv.z = sqrtf(xv.z + yv.z); sv.w = sqrtf(xv.w + yv.w);
        *(float4*)(sV + r*256 + dq) = sv;
        *(float4*)(sH + r*256 + dq) = zz;
    }
    __syncthreads();

    const int c0 = tid & 63;
    const int r0 = (tid >> 6) * 8;
    float accM[8][4], accS[8][4];
#pragma unroll
    for (int r = 0; r < 8; r++)
#pragma unroll
        for (int k = 0; k < 4; k++) { accM[r][k] = 0.f; accS[r][k] = 0.f; }

#pragma unroll 2
    for (int d = 0; d < 256; d++) {
        float wm[4], wc[4];
#pragma unroll
        for (int k = 0; k < 4; k++) {
            wm[k] = g_WMEt[d*256 + c0 + 64*k];
            wc[k] = g_WCEt[d*256 + c0 + 64*k];
        }
        float xm[8], xv[8], xh[8];
#pragma unroll
        for (int r = 0; r < 8; r++) {
            xm[r] = sX[(r0+r)*256 + d];
            xv[r] = sV[(r0+r)*256 + d];
            xh[r] = sH[(r0+r)*256 + d];
        }
#pragma unroll
        for (int r = 0; r < 8; r++)
#pragma unroll
            for (int k = 0; k < 4; k++) {
                accM[r][k] = fmaf(xm[r], wm[k], accM[r][k]);
                accM[r][k] = fmaf(xh[r], wc[k], accM[r][k]);
                accS[r][k] = fmaf(xv[r], wm[k], accS[r][k]);
            }
    }
#pragma unroll
    for (int r = 0; r < 8; r++)
#pragma unroll
        for (int k = 0; k < 4; k++) {
            const size_t o = (size_t)(tok0 + r0 + r)*256 + c0 + 64*k;
            out_means[o] = accM[r][k];
            out_stds[o]  = accS[r][k];
        }
}

// ---------------- launch ----------------
extern "C" void kernel_launch(void* const* d_in, const int* in_sizes, int n_in,
                              void* d_out, int out_size) {
    const float* Z   = (const float*)d_in[0];
    const float* obs = (const float*)d_in[1];
    const float* D   = (const float*)d_in[2];
    const float* cW  = (const float*)d_in[3];
    const float* cb  = (const float*)d_in[4];
    const float* E_w = (const float*)d_in[5];
    const float* B_w = (const float*)d_in[6];
    const float* C_w = (const float*)d_in[7];
    const float* M_w = (const float*)d_in[8];
    const float* imp = (const float*)d_in[9];
    const float* ilv = (const float*)d_in[10];
    const float* ylv = (const float*)d_in[11];

    float* out        = (float*)d_out;
    float* out_means  = out;
    float* out_stds   = out + (size_t)BTn * LDn;
    float* out_alphas = out + 2 * (size_t)BTn * LDn;

    cudaFuncSetAttribute(k_token, cudaFuncAttributeMaxDynamicSharedMemorySize, SMEM_TOKEN);
    cudaFuncSetAttribute(k_out,   cudaFuncAttributeMaxDynamicSharedMemorySize, SMEM_OUT);

    k_pre_small<<<1, 512>>>(E_w, D, imp, ilv, ylv);
    k_pre_transpose<<<dim3(8,8), dim3(32,32)>>>(B_w);
    k_pre_gemm<<<dim3(8,8,2), dim3(32,32)>>>(E_w, M_w, C_w);
    k_token<<<BTn/32, 256, SMEM_TOKEN>>>(Z, obs, cW, cb, out_alphas);
    k_scan1<<<Bn*NCHUNK, 512>>>();
    k_scan2<<<Bn, 512>>>();
    k_scan3<<<Bn*NCHUNK, 512>>>();
    k_out<<<BTn/64, 512, SMEM_OUT>>>(Z, out_means, out_stds);
}

// round 2
// speedup vs baseline: 1.3614x; 1.3614x over previous
#include <cuda_runtime.h>
#include <math.h>

#define EPSF 1e-6f
#define Bn 16
#define Tn 2048
#define LDn 256
#define NBn 32
#define BTn (Bn*Tn)
#define NCHUNK 64
#define CLEN 32

typedef unsigned long long ull;

__device__ __forceinline__ void ffma2(ull& d, ull a, ull b) {
    asm("fma.rn.f32x2 %0, %1, %2, %0;" : "+l"(d) : "l"(a), "l"(b));
}
__device__ __forceinline__ ull bc2(float x) {
    ull r; asm("mov.b64 %0, {%1, %1};" : "=l"(r) : "f"(x)); return r;
}
__device__ __forceinline__ float2 u2f(ull v) {
    float2 f; asm("mov.b64 {%0, %1}, %2;" : "=f"(f.x), "=f"(f.y) : "l"(v)); return f;
}

// -------- scratch (device globals: allocation-free) --------
__device__ float g_eA[(size_t)BTn*LDn];      // 32 MB: exp(A*t)
__device__ float g_inv[(size_t)BTn*LDn];     // 32 MB: 1/A
__device__ float g_aggA[Bn*NCHUNK*512];
__device__ float g_aggB[Bn*NCHUNK*512];
__device__ float g_carry[Bn*NCHUNK*512];
__device__ float g_Bt[LDn*LDn];              // B_w transposed: [d][e]
__device__ float g_WMEt[LDn*LDn];            // (M_w@E_w)^T : [d][f]
__device__ float g_WCEt[LDn*LDn];            // (C_w@E_w)^T : [d][f]
__device__ float g_WBCt[LDn*NBn];            // folded logit weights [d][n]
__device__ float g_Abasis[NBn*LDn];
__device__ float g_initmv[512];
__device__ float g_yvar[LDn];

// ---------------- precompute: vectors + A_basis ----------------
__global__ void k_pre_small(const float* __restrict__ E_w, const float* __restrict__ D,
                            const float* __restrict__ imp, const float* __restrict__ ilv,
                            const float* __restrict__ ylv) {
    const int tid = threadIdx.x;
    if (tid < 256) {
        float s = 0.f;
        for (int k = 0; k < 256; k++) s = fmaf(E_w[k*256 + tid], imp[k], s);
        g_initmv[tid] = s;
        g_yvar[tid] = expf(ylv[tid]) + EPSF;
    } else {
        const int i = tid - 256;
        float s = 0.f;
        for (int k = 0; k < 256; k++) {
            float e = E_w[k*256 + i];
            s = fmaf(e*e, expf(ilv[k]) + EPSF, s);
        }
        g_initmv[256 + i] = s;
    }
    for (int idx = tid; idx < NBn*LDn; idx += 512)
        g_Abasis[idx] = -(expf(D[idx]) + EPSF);
}

// ---------------- precompute: transpose B_w ----------------
__global__ void k_pre_transpose(const float* __restrict__ B_w) {
    __shared__ float t[32][33];
    const int tx = threadIdx.x, ty = threadIdx.y;
    const int e = blockIdx.y*32 + ty, d = blockIdx.x*32 + tx;
    t[ty][tx] = B_w[e*256 + d];
    __syncthreads();
    const int dd = blockIdx.x*32 + ty, ee = blockIdx.y*32 + tx;
    g_Bt[dd*256 + ee] = t[tx][ty];
}

// ---------------- precompute: W_ME^T, W_CE^T ----------------
__global__ void k_pre_gemm(const float* __restrict__ E_w, const float* __restrict__ M_w,
                           const float* __restrict__ C_w) {
    const float* X = (blockIdx.z == 0) ? M_w : C_w;
    float* out     = (blockIdx.z == 0) ? g_WMEt : g_WCEt;
    __shared__ float sE[32][33];
    __shared__ float sX[32][33];
    const int tx = threadIdx.x, ty = threadIdx.y;
    const int d0 = blockIdx.x*32, f0 = blockIdx.y*32;
    float acc = 0.f;
    for (int e0 = 0; e0 < 256; e0 += 32) {
        sE[ty][tx] = E_w[(e0+ty)*256 + d0 + tx];
        sX[ty][tx] = X[(f0+ty)*256 + e0 + tx];
        __syncthreads();
#pragma unroll
        for (int e = 0; e < 32; e++) acc = fmaf(sE[e][ty], sX[tx][e], acc);
        __syncthreads();
    }
    out[(d0+ty)*256 + f0 + tx] = acc;
}

// ---------------- precompute: folded logit weights ----------------
// g_WBCt[d][n] = sum_e B_w[e,d] * coeffW[n,e]
__global__ void k_pre_wbc(const float* __restrict__ B_w, const float* __restrict__ cW) {
    const int n = blockIdx.x;       // 32
    const int d = threadIdx.x;      // 256
    float s = 0.f;
#pragma unroll 4
    for (int e = 0; e < 256; e++)
        s = fmaf(B_w[e*256 + d], cW[n*256 + e], s);
    g_WBCt[d*32 + n] = s;
}

// ---------------- main per-token kernel ----------------
// 32 tokens/block = 1 scan chunk, 512 threads.
// alphas GEMM (f32x2) -> folded logits -> softmax -> A_mat -> exp + chunk aggregates
#define SMEM_TOKEN ((8704 + 8192 + 8192 + 1056 + 1056 + 32) * 4)
__global__ void __launch_bounds__(512, 2) k_token(const float* __restrict__ Z,
        const float* __restrict__ obs, const float* __restrict__ cb,
        float* __restrict__ alphas_out) {
    extern __shared__ float sm[];
    float* sZt   = sm;              // 256 x 34 : Z transposed [d][r]
    float* sAL   = sZt + 8704;      // 32 x 256 : alphas [r][c]
    float* sWB   = sAL + 8192;      // 32 x 256 : weight tile (later: partials)
    float* sLG   = sWB + 8192;      // 32 x 33  : logits
    float* sCoef = sLG + 1056;      // 32 x 33  : softmax coeffs
    float* sT    = sCoef + 1056;    // 32       : obs times

    const int tid = threadIdx.x;
    const int tok0 = blockIdx.x * 32;

    // ---- Z transposed load (coalesced read, strided smem write) ----
#pragma unroll
    for (int it = 0; it < 4; it++) {
        const int q = tid + it*512;           // float4 index (0..2047)
        const int r = q >> 6, cc = (q & 63) * 4;
        const float4 z4 = *(const float4*)(Z + (size_t)(tok0 + r)*256 + cc);
        sZt[(cc+0)*34 + r] = z4.x;
        sZt[(cc+1)*34 + r] = z4.y;
        sZt[(cc+2)*34 + r] = z4.z;
        sZt[(cc+3)*34 + r] = z4.w;
    }
    if (tid < 32) sT[tid] = obs[tok0 + tid];
    __syncthreads();

    const ull* pZ = (const ull*)sZt;          // [d][17] token pairs
    const int c4  = (tid & 63) * 4;
    const int rp0 = (tid >> 6) * 2;

    // ---- alphas GEMM: f32x2 along token pairs ----
    ull acc[2][4];
#pragma unroll
    for (int j = 0; j < 2; j++)
#pragma unroll
        for (int k = 0; k < 4; k++) acc[j][k] = 0ull;

    for (int dt = 0; dt < 8; dt++) {
#pragma unroll
        for (int it = 0; it < 4; it++) {
            const int q = tid + it*512;
            ((float4*)sWB)[q] = ((const float4*)(g_Bt + dt*8192))[q];
        }
        __syncthreads();
#pragma unroll 2
        for (int dd = 0; dd < 32; dd++) {
            const int d = dt*32 + dd;
            const float4 w4 = *(const float4*)(sWB + dd*256 + c4);
            const ull w0 = bc2(w4.x), w1 = bc2(w4.y), w2 = bc2(w4.z), w3 = bc2(w4.w);
            const ull x0 = pZ[d*17 + rp0], x1 = pZ[d*17 + rp0 + 1];
            ffma2(acc[0][0], x0, w0); ffma2(acc[0][1], x0, w1);
            ffma2(acc[0][2], x0, w2); ffma2(acc[0][3], x0, w3);
            ffma2(acc[1][0], x1, w0); ffma2(acc[1][1], x1, w1);
            ffma2(acc[1][2], x1, w2); ffma2(acc[1][3], x1, w3);
        }
        __syncthreads();
    }
    // epilogue: alphas -> smem + global
#pragma unroll
    for (int j = 0; j < 2; j++) {
        const int r0 = 2*(rp0 + j);
        const float2 a0 = u2f(acc[j][0]), a1 = u2f(acc[j][1]);
        const float2 a2 = u2f(acc[j][2]), a3 = u2f(acc[j][3]);
        const float4 lo = make_float4(a0.x, a1.x, a2.x, a3.x);
        const float4 hi = make_float4(a0.y, a1.y, a2.y, a3.y);
        *(float4*)(sAL + r0*256 + c4)     = lo;
        *(float4*)(sAL + (r0+1)*256 + c4) = hi;
        *(float4*)(alphas_out + (size_t)(tok0+r0)*256 + c4)   = lo;
        *(float4*)(alphas_out + (size_t)(tok0+r0+1)*256 + c4) = hi;
    }

    // ---- folded logits: logits[t][n] = Z[t,:] . WBC[:,n] ----
    {
        const int rpl = tid & 15;
        const int nn  = tid >> 4;     // 0..31
        ull accL = 0ull;
#pragma unroll 4
        for (int d = 0; d < 256; d++)
            ffma2(accL, pZ[d*17 + rpl], bc2(g_WBCt[d*32 + nn]));
        const float bias = cb[nn];
        const float2 lg = u2f(accL);
        sLG[(2*rpl)*33   + nn] = lg.x + bias;
        sLG[(2*rpl+1)*33 + nn] = lg.y + bias;
    }
    __syncthreads();

    // ---- softmax: 16 warps x 2 tokens, lane = basis ----
    {
        const int lane = tid & 31, warp = tid >> 5;
#pragma unroll
        for (int rr = 0; rr < 2; rr++) {
            const int r = warp*2 + rr;
            const float lg = sLG[r*33 + lane];
            float m = lg;
#pragma unroll
            for (int off = 16; off > 0; off >>= 1)
                m = fmaxf(m, __shfl_xor_sync(0xffffffffu, m, off));
            const float e = __expf(lg - m);
            float s = e;
#pragma unroll
            for (int off = 16; off > 0; off >>= 1)
                s += __shfl_xor_sync(0xffffffffu, s, off);
            sCoef[r*33 + lane] = e / s;
        }
    }
    __syncthreads();

    // ---- A_mat + exp terms + half-chunk aggregates ----
    const int c = tid & 255;
    const int h = tid >> 8;
    const int rbase = h * 16;
    float am[16];
#pragma unroll
    for (int rr = 0; rr < 16; rr++) am[rr] = 0.f;
#pragma unroll 4
    for (int n = 0; n < 32; n++) {
        const float ab = g_Abasis[n*256 + c];
#pragma unroll
        for (int rr = 0; rr < 16; rr++)
            am[rr] = fmaf(sCoef[(rbase+rr)*33 + n], ab, am[rr]);
    }
    float aAm = 1.f, bBm = 0.f, aAv = 1.f, bBv = 0.f;
#pragma unroll 4
    for (int rr = 0; rr < 16; rr++) {
        const int r = rbase + rr;
        const float a = am[rr];
        const float t = sT[r];
        const float eAm = __expf(a * t);
        const float inv = __fdividef(1.0f, a);
        const float al  = sAL[r*256 + c];
        const float eBm = (eAm - 1.f) * inv * al;
        const float eAv = eAm * eAm;
        const float eBv = 0.5f*(eAv - 1.f)*inv + EPSF;
        const size_t o = (size_t)(tok0 + r)*256 + c;
        g_eA[o]  = eAm;
        g_inv[o] = inv;
        bBm = fmaf(eAm, bBm, eBm); aAm *= eAm;
        bBv = fmaf(eAv, bBv, eBv); aAv *= eAv;
    }
    // combine the two 16-token halves: A=A1*A0, B=B1+A1*B0
    float* sPar = sWB;   // reuse weight-staging area
    sPar[(h*4+0)*256 + c] = aAm;
    sPar[(h*4+1)*256 + c] = bBm;
    sPar[(h*4+2)*256 + c] = aAv;
    sPar[(h*4+3)*256 + c] = bBv;
    __syncthreads();
    if (tid < 256) {
        const int bc = blockIdx.x;
        const float A0m = sPar[tid],          B0m = sPar[256 + tid];
        const float A0v = sPar[512 + tid],    B0v = sPar[768 + tid];
        const float A1m = sPar[1024 + tid],   B1m = sPar[1280 + tid];
        const float A1v = sPar[1536 + tid],   B1v = sPar[1792 + tid];
        g_aggA[bc*512 + tid]       = A1m * A0m;
        g_aggB[bc*512 + tid]       = fmaf(A1m, B0m, B1m);
        g_aggA[bc*512 + 256 + tid] = A1v * A0v;
        g_aggB[bc*512 + 256 + tid] = fmaf(A1v, B0v, B1v);
    }
}

// ---------------- scan over chunk aggregates ----------------
__global__ void k_scan2() {
    const int b = blockIdx.x;
    const int c = threadIdx.x;
    float s = g_initmv[c];
#pragma unroll 4
    for (int j = 0; j < NCHUNK; j++) {
        const int idx = (b*NCHUNK + j)*512 + c;
        g_carry[idx] = s;
        s = fmaf(g_aggA[idx], s, g_aggB[idx]);
    }
}

// ---------------- fused scan-apply + output GEMMs ----------------
// 32 tokens/block (= 1 chunk), 512 threads.
#define SMEM_FUSED ((8704*3 + 8192*2) * 4)
__global__ void __launch_bounds__(512, 1) k_fused(const float* __restrict__ Z,
        const float* __restrict__ alphas,
        float* __restrict__ out_means, float* __restrict__ out_stds) {
    extern __shared__ float sm[];
    float* sXt = sm;            // 256 x 34 mean-state [d][r]
    float* sVt = sXt + 8704;    // 256 x 34 sqrt(var+yvar)
    float* sHt = sVt + 8704;    // 256 x 34 Z
    float* sWM = sHt + 8704;    // 32 x 256
    float* sWC = sWM + 8192;    // 32 x 256

    const int tid  = threadIdx.x;
    const int bc   = blockIdx.x;
    const int tok0 = bc * 32;

    // ---- phase 1: apply carry, build transposed activation tiles ----
    {
        const int c = tid & 255;
        if ((tid >> 8) == 0) {
            float s = g_carry[bc*512 + c];
#pragma unroll 4
            for (int r = 0; r < 32; r++) {
                const size_t o = (size_t)(tok0 + r)*256 + c;
                const float eAm = g_eA[o], inv = g_inv[o], al = alphas[o];
                const float bm = (eAm - 1.f) * inv * al;
                s = fmaf(eAm, s, bm);
                sXt[c*34 + r] = s;
                sHt[c*34 + r] = Z[o];
            }
        } else {
            float s = g_carry[bc*512 + 256 + c];
            const float yv = g_yvar[c];
#pragma unroll 4
            for (int r = 0; r < 32; r++) {
                const size_t o = (size_t)(tok0 + r)*256 + c;
                const float eAm = g_eA[o], inv = g_inv[o];
                const float eAv = eAm * eAm;
                const float bv = 0.5f*(eAv - 1.f)*inv + EPSF;
                s = fmaf(eAv, s, bv);
                sVt[c*34 + r] = sqrtf(s + yv);
            }
        }
    }
    __syncthreads();

    // ---- phase 2: f32x2 GEMMs ----
    const ull* pX = (const ull*)sXt;
    const ull* pV = (const ull*)sVt;
    const ull* pH = (const ull*)sHt;
    const int c4  = (tid & 63) * 4;
    const int rp0 = (tid >> 6) * 2;
    ull accM[2][4], accS[2][4];
#pragma unroll
    for (int j = 0; j < 2; j++)
#pragma unroll
        for (int k = 0; k < 4; k++) { accM[j][k] = 0ull; accS[j][k] = 0ull; }

    for (int dt = 0; dt < 8; dt++) {
#pragma unroll
        for (int it = 0; it < 4; it++) {
            const int q = tid + it*512;
            ((float4*)sWM)[q] = ((const float4*)(g_WMEt + dt*8192))[q];
            ((float4*)sWC)[q] = ((const float4*)(g_WCEt + dt*8192))[q];
        }
        __syncthreads();
#pragma unroll 2
        for (int dd = 0; dd < 32; dd++) {
            const int d = dt*32 + dd;
            const float4 wm4 = *(const float4*)(sWM + dd*256 + c4);
            const float4 wc4 = *(const float4*)(sWC + dd*256 + c4);
            const ull wm0 = bc2(wm4.x), wm1 = bc2(wm4.y), wm2 = bc2(wm4.z), wm3 = bc2(wm4.w);
            const ull wc0 = bc2(wc4.x), wc1 = bc2(wc4.y), wc2 = bc2(wc4.z), wc3 = bc2(wc4.w);
            const ull xm0 = pX[d*17 + rp0], xm1 = pX[d*17 + rp0 + 1];
            const ull xv0 = pV[d*17 + rp0], xv1 = pV[d*17 + rp0 + 1];
            const ull xh0 = pH[d*17 + rp0], xh1 = pH[d*17 + rp0 + 1];
            ffma2(accM[0][0], xm0, wm0); ffma2(accM[0][1], xm0, wm1);
            ffma2(accM[0][2], xm0, wm2); ffma2(accM[0][3], xm0, wm3);
            ffma2(accM[0][0], xh0, wc0); ffma2(accM[0][1], xh0, wc1);
            ffma2(accM[0][2], xh0, wc2); ffma2(accM[0][3], xh0, wc3);
            ffma2(accS[0][0], xv0, wm0); ffma2(accS[0][1], xv0, wm1);
            ffma2(accS[0][2], xv0, wm2); ffma2(accS[0][3], xv0, wm3);
            ffma2(accM[1][0], xm1, wm0); ffma2(accM[1][1], xm1, wm1);
            ffma2(accM[1][2], xm1, wm2); ffma2(accM[1][3], xm1, wm3);
            ffma2(accM[1][0], xh1, wc0); ffma2(accM[1][1], xh1, wc1);
            ffma2(accM[1][2], xh1, wc2); ffma2(accM[1][3], xh1, wc3);
            ffma2(accS[1][0], xv1, wm0); ffma2(accS[1][1], xv1, wm1);
            ffma2(accS[1][2], xv1, wm2); ffma2(accS[1][3], xv1, wm3);
        }
        __syncthreads();
    }

    // ---- epilogue: float4 stores ----
#pragma unroll
    for (int j = 0; j < 2; j++) {
        const int r0 = 2*(rp0 + j);
        const float2 m0 = u2f(accM[j][0]), m1 = u2f(accM[j][1]);
        const float2 m2 = u2f(accM[j][2]), m3 = u2f(accM[j][3]);
        const float2 s0 = u2f(accS[j][0]), s1 = u2f(accS[j][1]);
        const float2 s2 = u2f(accS[j][2]), s3 = u2f(accS[j][3]);
        *(float4*)(out_means + (size_t)(tok0+r0)*256 + c4)   = make_float4(m0.x, m1.x, m2.x, m3.x);
        *(float4*)(out_means + (size_t)(tok0+r0+1)*256 + c4) = make_float4(m0.y, m1.y, m2.y, m3.y);
        *(float4*)(out_stds  + (size_t)(tok0+r0)*256 + c4)   = make_float4(s0.x, s1.x, s2.x, s3.x);
        *(float4*)(out_stds  + (size_t)(tok0+r0+1)*256 + c4) = make_float4(s0.y, s1.y, s2.y, s3.y);
    }
}

// ---------------- launch ----------------
extern "C" void kernel_launch(void* const* d_in, const int* in_sizes, int n_in,
                              void* d_out, int out_size) {
    const float* Z   = (const float*)d_in[0];
    const float* obs = (const float*)d_in[1];
    const float* D   = (const float*)d_in[2];
    const float* cW  = (const float*)d_in[3];
    const float* cb  = (const float*)d_in[4];
    const float* E_w = (const float*)d_in[5];
    const float* B_w = (const float*)d_in[6];
    const float* C_w = (const float*)d_in[7];
    const float* M_w = (const float*)d_in[8];
    const float* imp = (const float*)d_in[9];
    const float* ilv = (const float*)d_in[10];
    const float* ylv = (const float*)d_in[11];

    float* out        = (float*)d_out;
    float* out_means  = out;
    float* out_stds   = out + (size_t)BTn * LDn;
    float* out_alphas = out + 2 * (size_t)BTn * LDn;

    cudaFuncSetAttribute(k_token, cudaFuncAttributeMaxDynamicSharedMemorySize, SMEM_TOKEN);
    cudaFuncSetAttribute(k_fused, cudaFuncAttributeMaxDynamicSharedMemorySize, SMEM_FUSED);

    k_pre_small<<<1, 512>>>(E_w, D, imp, ilv, ylv);
    k_pre_transpose<<<dim3(8,8), dim3(32,32)>>>(B_w);
    k_pre_gemm<<<dim3(8,8,2), dim3(32,32)>>>(E_w, M_w, C_w);
    k_pre_wbc<<<NBn, 256>>>(B_w, cW);
    k_token<<<BTn/32, 512, SMEM_TOKEN>>>(Z, obs, cb, out_alphas);
    k_scan2<<<Bn, 512>>>();
    k_fused<<<BTn/32, 512, SMEM_FUSED>>>(Z, out_alphas, out_means, out_stds);
}